// round 16
// baseline (speedup 1.0000x reference)
#include <cuda_runtime.h>
#include <cuda_bf16.h>
#include <math.h>
#include <stdint.h>

#define G_   64
#define T_   10
#define H4_  1024
#define OFF_GAMMA 0
#define OFF_BETA  640
#define OFF_DELTA 164480
#define OFF_HN    328320
#define OFF_CN    361088

__device__ float g_h2  [G_ * T_ * 256];
__device__ float g_lin1[G_ * T_ * 256];
__device__ int   g_dummy;

__device__ __forceinline__ float fast_tanh(float x) {
    float r; asm("tanh.approx.f32 %0, %1;" : "=f"(r) : "f"(x)); return r;
}
__device__ __forceinline__ float sigf(float x) {
    return fmaf(fast_tanh(0.5f * x), 0.5f, 0.5f);
}
__device__ __forceinline__ void fma2(unsigned long long& a, unsigned long long x, unsigned long long y) {
    asm("fma.rn.f32x2 %0, %1, %2, %0;" : "+l"(a) : "l"(x), "l"(y));
}
__device__ __forceinline__ float unpack_sum(unsigned long long v) {
    unsigned int lo, hi;
    asm("mov.b64 {%0, %1}, %2;" : "=r"(lo), "=r"(hi) : "l"(v));
    return __uint_as_float(lo) + __uint_as_float(hi);
}
__device__ __forceinline__ unsigned int smem_u32(const void* p) {
    unsigned int a;
    asm("{ .reg .u64 t; cvta.to.shared.u64 t, %1; cvt.u32.u64 %0, t; }" : "=r"(a) : "l"(p));
    return a;
}
__device__ __forceinline__ void st_async_f32(unsigned int sa, unsigned int sb,
                                             unsigned int rk, float v) {
    asm volatile(
        "{ .reg .b32 ra, rb; mapa.shared::cluster.u32 ra, %0, %2;\n"
        "  mapa.shared::cluster.u32 rb, %1, %2;\n"
        "  st.async.shared::cluster.mbarrier::complete_tx::bytes.b32 [ra], %3, [rb]; }"
        :: "r"(sa), "r"(sb), "r"(rk), "f"(v) : "memory");
}
#define CLUSTER_SYNC() do { \
    asm volatile("barrier.cluster.arrive.aligned;" ::: "memory"); \
    asm volatile("barrier.cluster.wait.aligned;"   ::: "memory"); } while (0)
__device__ __forceinline__ void bulk_g2s(unsigned int d, const void* s,
                                         unsigned int b, unsigned int m) {
    asm volatile(
        "cp.async.bulk.shared::cluster.global.mbarrier::complete_tx::bytes [%0], [%1], %2, [%3];"
        :: "r"(d), "l"(s), "r"(b), "r"(m) : "memory");
}
__device__ __forceinline__ void mbar_init(unsigned int a, unsigned int c) {
    asm volatile("mbarrier.init.shared.b64 [%0], %1;" :: "r"(a), "r"(c) : "memory");
}
__device__ __forceinline__ void mbar_expect(unsigned int a, unsigned int b) {
    asm volatile("mbarrier.arrive.expect_tx.shared.b64 _, [%0], %1;" :: "r"(a), "r"(b) : "memory");
}
__device__ __forceinline__ void mbar_wait(unsigned int a, unsigned int p) {
    unsigned int d;
    do {
        asm volatile(
            "{ .reg .pred p; mbarrier.try_wait.parity.acquire.cta.shared::cta.b64 p, [%1], %2, 0x989680; selp.b32 %0,1,0,p; }"
            : "=r"(d) : "r"(a), "r"(p) : "memory");
    } while (!d);
}

__global__ void dummy_kernel(int tag) {
    if (tag == 12345 && threadIdx.x == 0) g_dummy = tag;
}

// ---------------------------------------------------------------------------
// 2-layer LSTM, TWO groups per 8-CTA cluster, interleaved recurrences.
// Grid 256 CTAs = 32 clusters. A: Whh registers. B: Whh SMEM-resident.
// ---------------------------------------------------------------------------
#define SMEM_BYTES 231584

__global__ void __cluster_dims__(8, 1, 1) __launch_bounds__(512, 1)
lstm2g_kernel(const float* __restrict__ Wih0, const float* __restrict__ Whh0,
              const float* __restrict__ bih0, const float* __restrict__ bhh0,
              const float* __restrict__ Wih1, const float* __restrict__ Whh1,
              const float* __restrict__ bih1, const float* __restrict__ bhh1,
              const float* __restrict__ data, float* __restrict__ out)
{
    extern __shared__ __align__(16) char smem[];
    float* s0     = (float*)(smem);
    float* s1     = (float*)(smem + 65536);
    float* s2     = (float*)(smem + 131072);
    float* xsA    = (float*)(smem + 196608);
    float* xsB    = (float*)(smem + 206848);
    float* xgpA   = (float*)(smem + 217088);
    float* xgpB   = (float*)(smem + 222208);
    float* h_bufA = (float*)(smem + 227328);
    float* h_bufB = (float*)(smem + 229376);
    const unsigned int mbT  = smem_u32(smem + 231424);  // 16 single-use TMA mbars
    const unsigned int mbFA = smem_u32(smem + 231552);  // fullA[2]
    const unsigned int mbFB = smem_u32(smem + 231568);  // fullB[2]
#define MB(i) (mbT + (unsigned)(i) * 8u)

    const int ci  = blockIdx.x >> 3;
    const int gA  = ci * 2, gB = gA + 1;
    const int crk = blockIdx.x & 7;
    const int tid = threadIdx.x;

    // xg map
    const int rl = tid >> 2, q = tid & 3;
    const int grow = (rl >> 5) * 256 + crk * 32 + (rl & 31);
    const int qh = q ^ (q << 1);
    // rec map (warp-local gates)
    const int l = tid & 31, w = tid >> 5;
    const int unit = w * 2 + ((l >> 4) & 1);
    const int q2 = l & 3;
    const int rl2 = ((l >> 2) & 3) * 32 + unit;
    const int qh2 = q2 ^ (q2 << 1);
    const int base = (l & 16) | q2;
    const int k = l & 15;
    const int gu = crk * 32 + unit;
    const int phys = gu ^ ((gu & 0xC0) >> 3);

    if (tid == 0) {
        #pragma unroll
        for (int i = 0; i < 16; i++) mbar_init(MB(i), 1);
        mbar_init(mbFA + 0, 1); mbar_init(mbFA + 8, 1);
        mbar_init(mbFB + 0, 1); mbar_init(mbFB + 8, 1);
        mbar_expect(mbFA + 0, 1024); mbar_expect(mbFA + 8, 1024);
        mbar_expect(mbFB + 0, 1024); mbar_expect(mbFB + 8, 1024);
    }
    __syncthreads();

    auto issue_half = [&](unsigned int m, float* buf, const float* M, int gg, int b0, int b1) {
        mbar_expect(m, 65536);
        bulk_g2s(smem_u32(buf),         M + ((size_t)gg * 1024 + b0 * 256 + crk * 32) * 256, 32768, m);
        bulk_g2s(smem_u32(buf) + 32768, M + ((size_t)gg * 1024 + b1 * 256 + crk * 32) * 256, 32768, m);
    };

    if (tid == 0) {
        issue_half(MB(0), s0, Wih0, gA, 0, 1);
        issue_half(MB(1), s1, Wih0, gA, 2, 3);
        issue_half(MB(2), s2, Wih0, gB, 0, 1);
    }

    for (int e = tid; e < 2 * T_ * 256; e += 512) {
        const int grp = e >= T_ * 256;
        const int e2 = grp ? e - T_ * 256 : e;
        const int t = e2 >> 8, u = e2 & 255;
        (grp ? xsB : xsA)[t * 256 + (u ^ ((u & 0xC0) >> 3))] =
            data[((size_t)t * G_ + (grp ? gB : gA)) * 256 + u];
    }
    if (tid < 256) { h_bufA[tid] = 0.0f; h_bufB[tid] = 0.0f; }
    __syncthreads();

    ulonglong2 wreg[16];

    auto run_xg = [&](const float* lob, const float* hib, const float* xs, float* xgp,
                      const float* bi, const float* bh, int gg) {
        const ulonglong2* ws = (const ulonglong2*)((rl < 64) ? (lob + rl * 256)
                                                             : (hib + (rl - 64) * 256));
        const ulonglong2* xs2 = (const ulonglong2*)xs;
        unsigned long long xa[T_];
        #pragma unroll
        for (int t = 0; t < T_; t++) xa[t] = 0ull;
        #pragma unroll 2
        for (int i = 0; i < 16; i++) {
            ulonglong2 wv = ws[16 * q + (i ^ q)];
            const int xi = 16 * q + (i ^ qh);
            #pragma unroll
            for (int t = 0; t < T_; t++) {
                ulonglong2 x = xs2[t * 64 + xi];
                fma2(xa[t], wv.x, x.x); fma2(xa[t], wv.y, x.y);
            }
        }
        const float bias = (q == 0)
            ? bi[(size_t)gg * H4_ + grow] + bh[(size_t)gg * H4_ + grow] : 0.0f;
        #pragma unroll
        for (int t = 0; t < T_; t++) {
            float s = unpack_sum(xa[t]);
            s += __shfl_xor_sync(0xffffffffu, s, 1);
            s += __shfl_xor_sync(0xffffffffu, s, 2);
            if (q == 0) xgp[t * 128 + rl] = s + bias;
        }
        __syncthreads();
    };
    auto load_wregA = [&](const float* lob, const float* hib) {
        const ulonglong2* src = (const ulonglong2*)((rl2 < 64) ? (lob + rl2 * 256)
                                                               : (hib + (rl2 - 64) * 256));
        #pragma unroll
        for (int i = 0; i < 16; i++) wreg[i] = src[16 * q2 + (i ^ q2)];
        __syncthreads();
    };

    const unsigned int hbA = smem_u32(h_bufA), hbB = smem_u32(h_bufB);
    unsigned int fA0 = 0, fA1 = 0, fB0 = 0, fB1 = 0;

    auto run_rec = [&](int layer, const float* wBlo, const float* wBhi,
                       unsigned int mBlo, unsigned int mBhi) {
        float* hdA = g_h2 + (size_t)gA * T_ * 256;
        float* hdB = g_h2 + (size_t)gB * T_ * 256;
        const ulonglong2* wsB = (const ulonglong2*)((rl2 < 64) ? (wBlo + rl2 * 256)
                                                               : (wBhi + (rl2 - 64) * 256));
        float cA = 0.0f, hA = 0.0f, cB = 0.0f, hB = 0.0f;
        for (int t = 0; t < T_; t++) {
            const int br = t & 1, bw = br ^ 1;
            // ---- group A (register weights) ----
            if (t > 0) {
                if (br) { mbar_wait(mbFA + 8, fA1); fA1 ^= 1; if (tid == 0) mbar_expect(mbFA + 8, 1024); }
                else    { mbar_wait(mbFA + 0, fA0); fA0 ^= 1; if (tid == 0) mbar_expect(mbFA + 0, 1024); }
            }
            if (layer == 0 && t > 0 && l < 16)
                xsA[(t - 1) * 256 + w * 16 + l] = h_bufA[br * 256 + w * 16 + l];
            {
                const ulonglong2* h2 = (const ulonglong2*)(h_bufA + br * 256);
                unsigned long long a0 = 0ull, a1 = 0ull;
                #pragma unroll
                for (int i = 0; i < 16; i++) {
                    ulonglong2 h = h2[16 * q2 + (i ^ qh2)];
                    fma2(a0, wreg[i].x, h.x); fma2(a1, wreg[i].y, h.y);
                }
                float s = unpack_sum(a0) + unpack_sum(a1);
                s += __shfl_xor_sync(0xffffffffu, s, 1);
                s += __shfl_xor_sync(0xffffffffu, s, 2);
                s += xgpA[t * 128 + rl2];
                float ig = __shfl_sync(0xffffffffu, s, base + 0);
                float fg = __shfl_sync(0xffffffffu, s, base + 4);
                float gg = __shfl_sync(0xffffffffu, s, base + 8);
                float og = __shfl_sync(0xffffffffu, s, base + 12);
                if (k < 8) {
                    cA = sigf(fg) * cA + sigf(ig) * fast_tanh(gg);
                    float h = sigf(og) * fast_tanh(cA);
                    hA = h;
                    if (layer && k == 0) hdA[(size_t)t * 256 + gu] = h;
                    st_async_f32(hbA + (unsigned)(bw * 256 + phys) * 4u,
                                 mbFA + (unsigned)bw * 8u, (unsigned)k, h);
                }
            }
            // ---- group B (SMEM weights) ----
            if (t == 0) mbar_wait(rl2 < 64 ? mBlo : mBhi, 0);
            if (t > 0) {
                if (br) { mbar_wait(mbFB + 8, fB1); fB1 ^= 1; if (tid == 0) mbar_expect(mbFB + 8, 1024); }
                else    { mbar_wait(mbFB + 0, fB0); fB0 ^= 1; if (tid == 0) mbar_expect(mbFB + 0, 1024); }
            }
            if (layer == 0 && t > 0 && l >= 16)
                xsB[(t - 1) * 256 + w * 16 + (l - 16)] = h_bufB[br * 256 + w * 16 + (l - 16)];
            {
                const ulonglong2* h2 = (const ulonglong2*)(h_bufB + br * 256);
                unsigned long long a0 = 0ull, a1 = 0ull;
                #pragma unroll 4
                for (int i = 0; i < 16; i++) {
                    ulonglong2 wv = wsB[16 * q2 + (i ^ q2)];
                    ulonglong2 h  = h2[16 * q2 + (i ^ qh2)];
                    fma2(a0, wv.x, h.x); fma2(a1, wv.y, h.y);
                }
                float s = unpack_sum(a0) + unpack_sum(a1);
                s += __shfl_xor_sync(0xffffffffu, s, 1);
                s += __shfl_xor_sync(0xffffffffu, s, 2);
                s += xgpB[t * 128 + rl2];
                float ig = __shfl_sync(0xffffffffu, s, base + 0);
                float fg = __shfl_sync(0xffffffffu, s, base + 4);
                float gg = __shfl_sync(0xffffffffu, s, base + 8);
                float og = __shfl_sync(0xffffffffu, s, base + 12);
                if (k >= 8) {
                    cB = sigf(fg) * cB + sigf(ig) * fast_tanh(gg);
                    float h = sigf(og) * fast_tanh(cB);
                    hB = h;
                    if (layer && k == 8) hdB[(size_t)t * 256 + gu] = h;
                    st_async_f32(hbB + (unsigned)(bw * 256 + phys) * 4u,
                                 mbFB + (unsigned)bw * 8u, (unsigned)(k - 8), h);
                }
            }
        }
        // drains (h(9) lands in buf0 of each group)
        mbar_wait(mbFA + 0, fA0); fA0 ^= 1; if (tid == 0) mbar_expect(mbFA + 0, 1024);
        if (layer == 0 && l < 16)  xsA[(T_ - 1) * 256 + w * 16 + l] = h_bufA[w * 16 + l];
        mbar_wait(mbFB + 0, fB0); fB0 ^= 1; if (tid == 0) mbar_expect(mbFB + 0, 1024);
        if (layer == 0 && l >= 16) xsB[(T_ - 1) * 256 + w * 16 + (l - 16)] = h_bufB[w * 16 + (l - 16)];
        __syncthreads();

        if (k == 0) {
            out[OFF_HN + (size_t)gA * 512 + layer * 256 + gu] = hA;
            out[OFF_CN + (size_t)gA * 512 + layer * 256 + gu] = cA;
        }
        if (k == 8) {
            out[OFF_HN + (size_t)gB * 512 + layer * 256 + gu] = hB;
            out[OFF_CN + (size_t)gB * 512 + layer * 256 + gu] = cB;
        }
    };

    // =================== Layer 0 ===================
    mbar_wait(rl < 64 ? MB(0) : MB(1), 0);
    run_xg(s0, s1, xsA, xgpA, bih0, bhh0, gA);          // consumes s0,s1
    if (tid == 0) { issue_half(MB(3), s0, Wih0, gB, 2, 3);
                    issue_half(MB(4), s1, Whh0, gA, 0, 1); }
    mbar_wait(rl < 64 ? MB(2) : MB(3), 0);
    run_xg(s2, s0, xsB, xgpB, bih0, bhh0, gB);          // consumes s2,s0
    if (tid == 0) { issue_half(MB(5), s2, Whh0, gA, 2, 3);
                    issue_half(MB(6), s0, Whh0, gB, 0, 1); }
    mbar_wait(rl2 < 64 ? MB(4) : MB(5), 0);
    load_wregA(s1, s2);                                  // consumes s1,s2
    if (tid == 0) { issue_half(MB(7), s1, Whh0, gB, 2, 3);
                    issue_half(MB(8), s2, Wih1, gA, 0, 1); }
    CLUSTER_SYNC();
    run_rec(0, s0, s1, MB(6), MB(7));                    // B weights s0/s1 held thru rec

    // =================== Layer 1 ===================
    if (tid == 0) { issue_half(MB(9),  s0, Wih1, gA, 2, 3);
                    issue_half(MB(10), s1, Wih1, gB, 0, 1); }
    if (tid < 256) { h_bufA[tid] = 0.0f; h_bufB[tid] = 0.0f; }
    mbar_wait(rl < 64 ? MB(8) : MB(9), 0);
    run_xg(s2, s0, xsA, xgpA, bih1, bhh1, gA);
    if (tid == 0) { issue_half(MB(11), s2, Wih1, gB, 2, 3);
                    issue_half(MB(12), s0, Whh1, gA, 0, 1); }
    mbar_wait(rl < 64 ? MB(10) : MB(11), 0);
    run_xg(s1, s2, xsB, xgpB, bih1, bhh1, gB);
    if (tid == 0) { issue_half(MB(13), s1, Whh1, gA, 2, 3);
                    issue_half(MB(14), s2, Whh1, gB, 0, 1); }
    mbar_wait(rl2 < 64 ? MB(12) : MB(13), 0);
    load_wregA(s0, s1);
    if (tid == 0) issue_half(MB(15), s0, Whh1, gB, 2, 3);
    CLUSTER_SYNC();
    run_rec(1, s2, s0, MB(14), MB(15));

    CLUSTER_SYNC();
}

// ---------------------------------------------------------------------------
// Fused tail (round-9 version, best measured). Grid: 64 x 512.
// ---------------------------------------------------------------------------
__global__ void __launch_bounds__(512)
tail_kernel(const float* __restrict__ Wlin, const float* __restrict__ blin,
            const float* __restrict__ W1, const float* __restrict__ b1,
            const float* __restrict__ W2, const float* __restrict__ b2,
            const float* __restrict__ Wd, const float* __restrict__ bd,
            float* __restrict__ out)
{
    __shared__ __align__(16) float hs [T_ * 256];
    __shared__ __align__(16) float fcs[T_ * 256];
    __shared__ float red[T_ * 8];
    const int g = blockIdx.x, tid = threadIdx.x;
    const int j = tid & 255, t0 = (tid >> 8) * 5;
    const int lane = tid & 31, w8 = (tid >> 5) & 7;

    {
        const float4* hp4 = (const float4*)(g_h2 + (size_t)g * T_ * 256);
        float4* hw = (float4*)hs;
        for (int e = tid; e < 640; e += 512) hw[e] = hp4[e];
    }
    __syncthreads();

    float acc[5];
    #pragma unroll
    for (int tt = 0; tt < 5; tt++) acc[tt] = 0.0f;
    {
        const float4* wl  = (const float4*)(Wlin + ((size_t)g * 256 + j) * 256);
        const float4* hs4 = (const float4*)hs;
        #pragma unroll 4
        for (int i4 = 0; i4 < 64; i4++) {
            float4 wv = wl[i4];
            #pragma unroll
            for (int tt = 0; tt < 5; tt++) {
                float4 f = hs4[(t0 + tt) * 64 + i4];
                acc[tt] += wv.x * f.x + wv.y * f.y + wv.z * f.z + wv.w * f.w;
            }
        }
    }
    const float bl = blin[(size_t)g * 256 + j];
    #pragma unroll
    for (int tt = 0; tt < 5; tt++) fcs[(t0 + tt) * 256 + j] = acc[tt] + bl;
    __syncthreads();

    float a1[5], a2[5];
    const float b1j = b1[j], b2j = b2[j];
    #pragma unroll
    for (int tt = 0; tt < 5; tt++) { a1[tt] = b1j; a2[tt] = b2j; }
    {
        const float4* w1r = (const float4*)(W1 + (size_t)j * 256);
        const float4* w2r = (const float4*)(W2 + (size_t)j * 256);
        const float4* f4  = (const float4*)fcs;
        #pragma unroll 4
        for (int i4 = 0; i4 < 64; i4++) {
            float4 w1 = w1r[i4], w2 = w2r[i4];
            #pragma unroll
            for (int tt = 0; tt < 5; tt++) {
                float4 f = f4[(t0 + tt) * 64 + i4];
                a1[tt] += w1.x * f.x + w1.y * f.y + w1.z * f.z + w1.w * f.w;
                a2[tt] += w2.x * f.x + w2.y * f.y + w2.z * f.z + w2.w * f.w;
            }
        }
    }
    const float wd = Wd[j];
    #pragma unroll
    for (int tt = 0; tt < 5; tt++) {
        const int t = t0 + tt;
        const size_t idx = ((size_t)g * T_ + t) * 256 + j;
        g_lin1[idx] = a1[tt];
        float x = a2[tt];
        out[OFF_BETA + idx] = (x > 20.0f) ? x : log1pf(__expf(x));
        float s = a1[tt] * wd;
        #pragma unroll
        for (int o = 16; o > 0; o >>= 1) s += __shfl_xor_sync(0xffffffffu, s, o);
        if (lane == 0) red[t * 8 + w8] = s;
    }
    __syncthreads();
    if (tid < T_) {
        float s = 0.0f;
        #pragma unroll
        for (int w2i = 0; w2i < 8; w2i++) s += red[tid * 8 + w2i];
        out[OFF_GAMMA + (size_t)g * T_ + tid] = s + bd[0];
    }
}

__global__ void softmax_kernel(float* __restrict__ out)
{
    const int t = blockIdx.x;
    const int j = blockIdx.y * 64 + threadIdx.x;
    float v[G_];
    float m = -1e30f;
    #pragma unroll
    for (int g = 0; g < G_; g++) {
        v[g] = g_lin1[((size_t)g * T_ + t) * 256 + j];
        m = fmaxf(m, v[g]);
    }
    float s = 0.0f;
    #pragma unroll
    for (int g = 0; g < G_; g++) { v[g] = __expf(v[g] - m); s += v[g]; }
    const float inv = __fdividef(1.0f, s);
    #pragma unroll
    for (int g = 0; g < G_; g++)
        out[OFF_DELTA + ((size_t)g * T_ + t) * 256 + j] = v[g] * inv;
}

extern "C" void kernel_launch(void* const* d_in, const int* in_sizes, int n_in,
                              void* d_out, int out_size)
{
    const float* data = (const float*)d_in[0];
    const float* Wih0 = (const float*)d_in[1];
    const float* Whh0 = (const float*)d_in[2];
    const float* bih0 = (const float*)d_in[3];
    const float* bhh0 = (const float*)d_in[4];
    const float* Wih1 = (const float*)d_in[5];
    const float* Whh1 = (const float*)d_in[6];
    const float* bih1 = (const float*)d_in[7];
    const float* bhh1 = (const float*)d_in[8];
    const float* Wlin = (const float*)d_in[9];
    const float* blin = (const float*)d_in[10];
    const float* W1   = (const float*)d_in[11];
    const float* b1   = (const float*)d_in[12];
    const float* W2   = (const float*)d_in[13];
    const float* b2   = (const float*)d_in[14];
    const float* Wd   = (const float*)d_in[15];
    const float* bd   = (const float*)d_in[16];
    float* out = (float*)d_out;

    cudaFuncSetAttribute(lstm2g_kernel,
                         cudaFuncAttributeMaxDynamicSharedMemorySize, SMEM_BYTES);

    // 2 dummies: the 4th launch (captured by ncu) is tail_kernel this round.
    dummy_kernel<<<1, 32>>>(0);
    dummy_kernel<<<1, 32>>>(1);

    lstm2g_kernel<<<G_ * 4, 512, SMEM_BYTES>>>(Wih0, Whh0, bih0, bhh0,
                                               Wih1, Whh1, bih1, bhh1, data, out);
    tail_kernel<<<64, 512>>>(Wlin, blin, W1, b1, W2, b2, Wd, bd, out);
    softmax_kernel<<<dim3(10, 4), 64>>>(out);
}